// round 16
// baseline (speedup 1.0000x reference)
#include <cuda_runtime.h>
#include <cuda_bf16.h>
#include <math.h>
#include <stdint.h>

#define NN 20000
#define EE 320000
#define HH 128
#define NTILES_N ((NN + 63) / 64)   /* 313 */
#define ETILE 128
#define NTILES_E (EE / ETILE)       /* 2500 */
#define GRIDN 148

extern __shared__ char smraw[];

/* ---------------- scratch (static device globals; no allocations) -------- */
__device__ float g_g1[NN * HH];
__device__ float g_g2[NN * HH];
__device__ float g_mi[NN * HH];
__device__ float g_tmp[NN * HH];
__device__ float g_dx[NN * 3];

/* ---------------- small helpers ------------------------------------------ */
__device__ __forceinline__ void red2(float* p, float a, float b) {
    asm volatile("red.global.add.v2.f32 [%0], {%1,%2};"
                 :: "l"(p), "f"(a), "f"(b) : "memory");
}
__device__ __forceinline__ uint32_t smem_u32(const void* p) {
    uint32_t a;
    asm("{ .reg .u64 t; cvta.to.shared.u64 t, %1; cvt.u32.u64 %0, t; }"
        : "=r"(a) : "l"(p));
    return a;
}
#define PACKBF2(res, a, b) \
    asm("cvt.rn.satfinite.bf16x2.f32 %0, %1, %2;" : "=r"(res) : "f"(b), "f"(a))
__device__ __forceinline__ void split2(float a0, float a1, uint32_t& hw, uint32_t& lw) {
    PACKBF2(hw, a0, a1);
    float h0 = __uint_as_float(hw << 16);
    float h1 = __uint_as_float(hw & 0xffff0000u);
    PACKBF2(lw, a0 - h0, a1 - h1);
}

/* ---------------- mma / ldmatrix ----------------------------------------- */
#define LDSM4(r, a) \
    asm volatile("ldmatrix.sync.aligned.m8n8.x4.shared.b16 {%0,%1,%2,%3},[%4];" \
        : "=r"((r)[0]), "=r"((r)[1]), "=r"((r)[2]), "=r"((r)[3]) : "r"(a))
#define MMA_B16(d, a, b0, b1) \
    asm volatile("mma.sync.aligned.m16n8k16.row.col.f32.bf16.bf16.f32 " \
        "{%0,%1,%2,%3},{%4,%5,%6,%7},{%8,%9},{%0,%1,%2,%3};" \
        : "+f"((d)[0]), "+f"((d)[1]), "+f"((d)[2]), "+f"((d)[3]) \
        : "r"((a)[0]), "r"((a)[1]), "r"((a)[2]), "r"((a)[3]), "r"(b0), "r"(b1))

__device__ __forceinline__ uint32_t pch(int c, int r) {
    return (uint32_t)((c & ~7) | ((c & 7) ^ (r & 7)));
}

/* warp GEMM: D[16*MBLK rows x 16*NJP cols] += A * B^T, acc[MBLK*2*NJP][4] */
template<int KSTEPS, bool X3, int CA, int CB, int MBLK, int NJP>
__device__ __forceinline__ void mma_gemm(const char* aH, const char* aL,
                                         const char* bH, const char* bL,
                                         float acc[][4], int wm, int wn, int lane) {
    int ar7 = lane & 7;
    int arow_in = ((lane >> 3) & 1) * 8 + ar7;
    int acoff = lane >> 4;
    int brow_l = ((lane >> 4) & 1) * 8 + ar7;
    int bcoff = (lane >> 3) & 1;
    uint32_t aHb = smem_u32(aH);
    uint32_t aLb = X3 ? smem_u32(aL) : 0u;
    uint32_t bHb = smem_u32(bH);
    uint32_t bLb = X3 ? smem_u32(bL) : 0u;
#pragma unroll
    for (int ks = 0; ks < KSTEPS; ks++) {
        uint32_t ah[MBLK][4], al[MBLK][4];
        uint32_t achoff = pch(2 * ks + acoff, ar7) * 16;
#pragma unroll
        for (int mb = 0; mb < MBLK; mb++) {
            int arow = 16 * MBLK * wm + 16 * mb + arow_in;
            LDSM4(ah[mb], aHb + (uint32_t)(arow * CA) + achoff);
            if (X3) LDSM4(al[mb], aLb + (uint32_t)(arow * CA) + achoff);
        }
        uint32_t boff = pch(2 * ks + bcoff, ar7) * 16;
#pragma unroll
        for (int jp = 0; jp < NJP; jp++) {
            uint32_t brb = (uint32_t)((wn * (16 * NJP) + jp * 16 + brow_l) * CB) + boff;
            uint32_t bh[4], bl[4];
            LDSM4(bh, bHb + brb);
            if (X3) LDSM4(bl, bLb + brb);
#pragma unroll
            for (int mb = 0; mb < MBLK; mb++) {
                float* a0 = acc[mb * 2 * NJP + 2 * jp];
                float* a1 = acc[mb * 2 * NJP + 2 * jp + 1];
                MMA_B16(a0, ah[mb], bh[0], bh[1]);
                MMA_B16(a1, ah[mb], bh[2], bh[3]);
                if (X3) {
                    MMA_B16(a0, al[mb], bh[0], bh[1]);
                    MMA_B16(a1, al[mb], bh[2], bh[3]);
                    MMA_B16(a0, ah[mb], bl[0], bl[1]);
                    MMA_B16(a1, ah[mb], bl[2], bl[3]);
                }
            }
        }
    }
}

/* ================= kernel A: node precompute (MMA, grid-stride) ========== */
#define P_W1H 0
#define P_W1L 32768
#define P_W2H 65536
#define P_W2L 98304
#define P_AH  131072
#define P_AL  147456
#define P_TOT 163840

__global__ void __launch_bounds__(512, 1)
k_node_pre(const float* __restrict__ h, const float* __restrict__ ew1,
           const float* __restrict__ eb1) {
    char* sm = smraw;
    int tid = threadIdx.x, lane = tid & 31, wid = tid >> 5;
    int wm = wid >> 2, wn = wid & 3;
    int gtid = blockIdx.x * 512 + tid;

    for (int i = gtid; i < NN * HH; i += GRIDN * 512) g_mi[i] = 0.f;
    for (int i = gtid; i < NN * 3; i += GRIDN * 512) g_dx[i] = 0.f;

    for (int i = tid; i < 128 * 64; i += 512) {
        int n = i >> 6, kp = i & 63, k = 2 * kp;
        uint32_t off = (uint32_t)(n * 256) + pch(k >> 3, n) * 16 + (k & 7) * 2;
        uint32_t hw, lw;
        split2(ew1[(48 + k) * 128 + n], ew1[(49 + k) * 128 + n], hw, lw);
        *(uint32_t*)(sm + P_W1H + off) = hw;
        *(uint32_t*)(sm + P_W1L + off) = lw;
        split2(ew1[(176 + k) * 128 + n], ew1[(177 + k) * 128 + n], hw, lw);
        *(uint32_t*)(sm + P_W2H + off) = hw;
        *(uint32_t*)(sm + P_W2L + off) = lw;
    }
    __syncthreads();

    int r0 = 16 * wm + (lane >> 2), r1 = r0 + 8;

    for (int t = blockIdx.x; t < NTILES_N; t += GRIDN) {
        int n0 = t * 64;
        for (int i = tid; i < 64 * 64; i += 512) {
            int r = i >> 6, kp = i & 63, k = 2 * kp, n = n0 + r;
            float2 v = (n < NN) ? *(const float2*)&h[(size_t)n * 128 + k]
                                : make_float2(0.f, 0.f);
            uint32_t hw, lw; split2(v.x, v.y, hw, lw);
            uint32_t off = (uint32_t)(r * 256) + pch(k >> 3, r) * 16 + (k & 7) * 2;
            *(uint32_t*)(sm + P_AH + off) = hw;
            *(uint32_t*)(sm + P_AL + off) = lw;
        }
        __syncthreads();

        float acc[4][4];
#pragma unroll
        for (int j = 0; j < 4; j++)
#pragma unroll
            for (int q = 0; q < 4; q++) acc[j][q] = 0.f;
        mma_gemm<8, true, 256, 256, 1, 2>(sm + P_AH, sm + P_AL,
                                          sm + P_W1H, sm + P_W1L, acc, wm, wn, lane);
#pragma unroll
        for (int j = 0; j < 4; j++) {
            int col = 32 * wn + 8 * j + 2 * (lane & 3);
            float2 b = __ldg((const float2*)(eb1 + col));
            if (n0 + r0 < NN)
                *(float2*)&g_g1[(size_t)(n0 + r0) * 128 + col] =
                    make_float2(acc[j][0] + b.x, acc[j][1] + b.y);
            if (n0 + r1 < NN)
                *(float2*)&g_g1[(size_t)(n0 + r1) * 128 + col] =
                    make_float2(acc[j][2] + b.x, acc[j][3] + b.y);
        }
#pragma unroll
        for (int j = 0; j < 4; j++)
#pragma unroll
            for (int q = 0; q < 4; q++) acc[j][q] = 0.f;
        mma_gemm<8, true, 256, 256, 1, 2>(sm + P_AH, sm + P_AL,
                                          sm + P_W2H, sm + P_W2L, acc, wm, wn, lane);
#pragma unroll
        for (int j = 0; j < 4; j++) {
            int col = 32 * wn + 8 * j + 2 * (lane & 3);
            if (n0 + r0 < NN)
                *(float2*)&g_g2[(size_t)(n0 + r0) * 128 + col] =
                    make_float2(acc[j][0], acc[j][1]);
            if (n0 + r1 < NN)
                *(float2*)&g_g2[(size_t)(n0 + r1) * 128 + col] =
                    make_float2(acc[j][2], acc[j][3]);
        }
        __syncthreads();
    }
}

/* ================= kernel B: edge pipeline (4 syncs/tile) ================ */
#define SB_PDB   512
#define SB_FEATH 2560
#define SB_FEATL 18944
#define SB_BUFM  2560
#define SB_TH    35328
#define SB_TL    68096
#define SB_W1H   100864
#define SB_W1L   117248
#define SB_W2H   133632
#define SB_W2L   166400
#define SB_W3    199168
#define SB_TOTAL 231936

__global__ void __launch_bounds__(512, 1)
k_edge(const float* __restrict__ x, const float* __restrict__ eattr,
       const float* __restrict__ ew1, const float* __restrict__ ew2,
       const float* __restrict__ eb2, const float* __restrict__ infw,
       const float* __restrict__ infb, const float* __restrict__ xw1,
       const float* __restrict__ xb1, const float* __restrict__ xw2,
       const float* __restrict__ xb2, const int* __restrict__ eidx) {
    char* sm = smraw;
    float* pdb = (float*)(sm + SB_PDB);

    int tid = threadIdx.x;
    int lane = tid & 31;
    int wid = tid >> 5;
    int wm = wid >> 2, wn = wid & 3;

    for (int i = tid; i < 128 * 64; i += 512) {
        int n = i >> 6, k = i & 63;
        float v = (k < 48) ? ew1[k * 128 + n] : 0.f;
        __nv_bfloat16 hb = __float2bfloat16(v);
        uint32_t off = (uint32_t)(n * 128) + pch(k >> 3, n) * 16 + (k & 7) * 2;
        *(__nv_bfloat16*)(sm + SB_W1H + off) = hb;
        *(__nv_bfloat16*)(sm + SB_W1L + off) =
            __float2bfloat16(v - __bfloat162float(hb));
    }
    for (int i = tid; i < 128 * 128; i += 512) {
        int n = i >> 7, k = i & 127;
        uint32_t off = (uint32_t)(n * 256) + pch(k >> 3, n) * 16 + (k & 7) * 2;
        float v = ew2[k * 128 + n];
        __nv_bfloat16 hb = __float2bfloat16(v);
        *(__nv_bfloat16*)(sm + SB_W2H + off) = hb;
        *(__nv_bfloat16*)(sm + SB_W2L + off) =
            __float2bfloat16(v - __bfloat162float(hb));
        *(__nv_bfloat16*)(sm + SB_W3 + off) = __float2bfloat16(xw1[k * 128 + n]);
    }
    __syncthreads();

    const float infbv = infb[0];
    const float xb2v  = xb2[0];
    const float step  = 100.0f / 19.0f;
    const float coeff = -0.5f / (step * step);

    /* C_k = exp(-k*k/2), k = 0..19 (compile-time constants; 0 past underflow) */
    const float CK[20] = {
        1.0f,            6.0653066e-1f,  1.3533528e-1f,  1.1108997e-2f,
        3.3546263e-4f,   3.7266532e-6f,  1.5229979e-8f,  2.2897348e-11f,
        1.2664166e-14f,  2.5767045e-18f, 1.9287498e-22f, 5.3110922e-27f,
        5.3801861e-32f,  2.0050131e-37f, 0.0f,           0.0f,
        0.0f,            0.0f,           0.0f,           0.0f };

    int rowq[4];
#pragma unroll
    for (int q = 0; q < 4; q++)
        rowq[q] = 32 * wm + 16 * (q >> 1) + (lane >> 2) + 8 * (q & 1);

    for (int tile = blockIdx.x; tile < NTILES_E; tile += gridDim.x) {
        __syncthreads();                      /* s0: prev GEMM3 bufM reads done */
        int e0 = tile * ETILE;

        if (tid < 128) {
            int e = e0 + tid;
            int d = __ldg(&eidx[e]), s = __ldg(&eidx[EE + e]);
            float rx = x[d * 3 + 0] - x[s * 3 + 0];
            float ry = x[d * 3 + 1] - x[s * 3 + 1];
            float rz = x[d * 3 + 2] - x[s * 3 + 2];
            float l2 = sqrtf(rx * rx + ry * ry + rz * rz);
            /* rbf_k = A * B^k * C_k  (A=exp(coeff*l2^2), B=exp(l2/step)) */
            float Bv = expf(l2 * (1.0f / step));
            float tacc = expf(coeff * l2 * l2);
#pragma unroll
            for (int kk = 0; kk < 10; kk++) {
                int w = 14 + kk;
                float r0v = tacc * CK[2 * kk];
                tacc *= Bv;
                float r1v = tacc * CK[2 * kk + 1];
                tacc *= Bv;
                uint32_t hw, lw;
                split2(r0v, r1v, hw, lw);
                uint32_t off = (uint32_t)(tid * 128) + pch(w >> 2, tid) * 16 + (w & 3) * 4;
                *(uint32_t*)(sm + SB_FEATH + off) = hw;
                *(uint32_t*)(sm + SB_FEATL + off) = lw;
            }
        }
        for (int i = tid; i < 128 * 14; i += 512) {
            int e = i / 14, w = i - 14 * e;
            float2 t = *(const float2*)&eattr[(size_t)(e0 + e) * 28 + 2 * w];
            uint32_t hw, lw; split2(t.x, t.y, hw, lw);
            uint32_t off = (uint32_t)(e * 128) + pch(w >> 2, e) * 16 + (w & 3) * 4;
            *(uint32_t*)(sm + SB_FEATH + off) = hw;
            *(uint32_t*)(sm + SB_FEATL + off) = lw;
        }
        __syncthreads();                      /* s2: feat ready */

        int dR[4], sR[4];
#pragma unroll
        for (int q = 0; q < 4; q++) {
            dR[q] = __ldg(&eidx[e0 + rowq[q]]);
            sR[q] = __ldg(&eidx[EE + e0 + rowq[q]]);
        }

        /* ---- GEMM1 (K=48, bf16x3) ---- */
        float acc[8][4];
#pragma unroll
        for (int j = 0; j < 8; j++)
#pragma unroll
            for (int q = 0; q < 4; q++) acc[j][q] = 0.f;
        mma_gemm<3, true, 128, 128, 2, 2>(sm + SB_FEATH, sm + SB_FEATL,
                                          sm + SB_W1H, sm + SB_W1L, acc, wm, wn, lane);

        /* ---- ep1: t1 = relu(D + g1[d] + g2[s]) -> TH/TL ---- */
#pragma unroll
        for (int q = 0; q < 4; q++) {
            const float* g1p = g_g1 + (size_t)dR[q] * 128;
            const float* g2p = g_g2 + (size_t)sR[q] * 128;
            int row = rowq[q];
            int e01 = (q & 1) * 2;
#pragma unroll
            for (int j = 0; j < 4; j++) {
                int col = 32 * wn + 8 * j + 2 * (lane & 3);
                float2 a = *(const float2*)(g1p + col);
                float2 b = *(const float2*)(g2p + col);
                float* ac = acc[(q >> 1) * 4 + j];
                float v0 = fmaxf(ac[e01] + a.x + b.x, 0.f);
                float v1 = fmaxf(ac[e01 + 1] + a.y + b.y, 0.f);
                uint32_t hw, lw; split2(v0, v1, hw, lw);
                uint32_t off = (uint32_t)(row * 256) + pch(col >> 3, row) * 16 + (col & 7) * 2;
                *(uint32_t*)(sm + SB_TH + off) = hw;
                *(uint32_t*)(sm + SB_TL + off) = lw;
            }
        }
        __syncthreads();                      /* s_T */

        /* ---- GEMM2 (K=128, bf16x3) ---- */
#pragma unroll
        for (int j = 0; j < 8; j++)
#pragma unroll
            for (int q = 0; q < 4; q++) acc[j][q] = 0.f;
        mma_gemm<8, true, 256, 256, 2, 2>(sm + SB_TH, sm + SB_TL,
                                          sm + SB_W2H, sm + SB_W2L, acc, wm, wn, lane);

        /* ---- ep2a: mij = relu(D+eb2); gate partials -> pdb; bufM ---- */
        float pdv[4] = {0.f, 0.f, 0.f, 0.f};
#pragma unroll
        for (int j = 0; j < 4; j++) {
            int col = 32 * wn + 8 * j + 2 * (lane & 3);
            float2 be = __ldg((const float2*)(eb2 + col));
            float2 iw = __ldg((const float2*)(infw + col));
#pragma unroll
            for (int q = 0; q < 4; q++) {
                float* ac = acc[(q >> 1) * 4 + j];
                int e01 = (q & 1) * 2;
                float m0 = fmaxf(ac[e01] + be.x, 0.f);
                float m1 = fmaxf(ac[e01 + 1] + be.y, 0.f);
                ac[e01] = m0; ac[e01 + 1] = m1;
                pdv[q] += m0 * iw.x + m1 * iw.y;
                uint32_t w; PACKBF2(w, m0, m1);
                int row = rowq[q];
                uint32_t off = (uint32_t)(row * 256) + pch(col >> 3, row) * 16 + (col & 7) * 2;
                *(uint32_t*)(sm + SB_BUFM + off) = w;
            }
        }
#pragma unroll
        for (int o = 1; o <= 2; o <<= 1)
#pragma unroll
            for (int q = 0; q < 4; q++)
                pdv[q] += __shfl_xor_sync(0xffffffffu, pdv[q], o);
        if ((lane & 3) == 0) {
#pragma unroll
            for (int q = 0; q < 4; q++)
                pdb[rowq[q] * 4 + wn] = pdv[q];
        }
        __syncthreads();                      /* s_pd */

        /* ---- ep2b: eij; scatter mi ---- */
#pragma unroll
        for (int q = 0; q < 4; q++) {
            float4 p = *(const float4*)(pdb + rowq[q] * 4);
            float eij = 1.f / (1.f + expf(-(p.x + p.y + p.z + p.w + infbv)));
            float* mip = g_mi + (size_t)dR[q] * 128;
            int e01 = (q & 1) * 2;
#pragma unroll
            for (int j = 0; j < 4; j++) {
                int col = 32 * wn + 8 * j + 2 * (lane & 3);
                float* ac = acc[(q >> 1) * 4 + j];
                red2(mip + col, ac[e01] * eij, ac[e01 + 1] * eij);
            }
        }

        /* ---- GEMM3 (K=128, bf16 x1) ---- */
#pragma unroll
        for (int j = 0; j < 8; j++)
#pragma unroll
            for (int q = 0; q < 4; q++) acc[j][q] = 0.f;
        mma_gemm<8, false, 256, 256, 2, 2>(sm + SB_BUFM, 0,
                                           sm + SB_W3, 0, acc, wm, wn, lane);

        /* ---- ep3: per-wn xg partial scattered directly to g_dx ---- */
        float qv[4] = {0.f, 0.f, 0.f, 0.f};
#pragma unroll
        for (int j = 0; j < 4; j++) {
            int col = 32 * wn + 8 * j + 2 * (lane & 3);
            float2 xb = __ldg((const float2*)(xb1 + col));
            float2 xw = __ldg((const float2*)(xw2 + col));
#pragma unroll
            for (int q = 0; q < 4; q++) {
                float* ac = acc[(q >> 1) * 4 + j];
                int e01 = (q & 1) * 2;
                qv[q] += fmaxf(ac[e01] + xb.x, 0.f) * xw.x
                       + fmaxf(ac[e01 + 1] + xb.y, 0.f) * xw.y;
            }
        }
#pragma unroll
        for (int o = 1; o <= 2; o <<= 1)
#pragma unroll
            for (int q = 0; q < 4; q++)
                qv[q] += __shfl_xor_sync(0xffffffffu, qv[q], o);
        if ((lane & 3) == 0) {
            float base = (wn == 0) ? xb2v : 0.f;
#pragma unroll
            for (int q = 0; q < 4; q++) {
                float xg = qv[q] + base;
                int d = dR[q], s = sR[q];
                float rx = __ldg(&x[d * 3 + 0]) - __ldg(&x[s * 3 + 0]);
                float ry = __ldg(&x[d * 3 + 1]) - __ldg(&x[s * 3 + 1]);
                float rz = __ldg(&x[d * 3 + 2]) - __ldg(&x[s * 3 + 2]);
                atomicAdd(&g_dx[d * 3 + 0], rx * xg);
                atomicAdd(&g_dx[d * 3 + 1], ry * xg);
                atomicAdd(&g_dx[d * 3 + 2], rz * xg);
            }
        }
    }
}

/* ================= kernel C1: hidden = relu([mi,h]@nw1+nb1) (MMA) ======== */
#define N1_WH 0
#define N1_WL 65536
#define N1_AH 131072
#define N1_AL 163840
#define N1_TOT 196608

__global__ void __launch_bounds__(512, 1)
k_node1(const float* __restrict__ h, const float* __restrict__ nw1,
        const float* __restrict__ nb1) {
    char* sm = smraw;
    int tid = threadIdx.x, lane = tid & 31, wid = tid >> 5;
    int wm = wid >> 2, wn = wid & 3;

    for (int i = tid; i < 128 * 128; i += 512) {
        int n = i >> 7, kp = i & 127, k = 2 * kp;
        uint32_t off = (uint32_t)(n * 512) + pch(k >> 3, n) * 16 + (k & 7) * 2;
        uint32_t hw, lw;
        split2(nw1[k * 128 + n], nw1[(k + 1) * 128 + n], hw, lw);
        *(uint32_t*)(sm + N1_WH + off) = hw;
        *(uint32_t*)(sm + N1_WL + off) = lw;
    }
    __syncthreads();

    int r0 = 16 * wm + (lane >> 2), r1 = r0 + 8;

    for (int t = blockIdx.x; t < NTILES_N; t += GRIDN) {
        int n0 = t * 64;
        for (int i = tid; i < 64 * 128; i += 512) {
            int r = i >> 7, kp = i & 127, k = 2 * kp, n = n0 + r;
            float2 v = make_float2(0.f, 0.f);
            if (n < NN)
                v = (k < 128) ? *(const float2*)&g_mi[(size_t)n * 128 + k]
                              : *(const float2*)&h[(size_t)n * 128 + (k - 128)];
            uint32_t hw, lw; split2(v.x, v.y, hw, lw);
            uint32_t off = (uint32_t)(r * 512) + pch(k >> 3, r) * 16 + (k & 7) * 2;
            *(uint32_t*)(sm + N1_AH + off) = hw;
            *(uint32_t*)(sm + N1_AL + off) = lw;
        }
        __syncthreads();

        float acc[4][4];
#pragma unroll
        for (int j = 0; j < 4; j++)
#pragma unroll
            for (int q = 0; q < 4; q++) acc[j][q] = 0.f;
        mma_gemm<16, true, 512, 512, 1, 2>(sm + N1_AH, sm + N1_AL,
                                           sm + N1_WH, sm + N1_WL, acc, wm, wn, lane);
#pragma unroll
        for (int j = 0; j < 4; j++) {
            int col = 32 * wn + 8 * j + 2 * (lane & 3);
            float2 b = __ldg((const float2*)(nb1 + col));
            if (n0 + r0 < NN)
                *(float2*)&g_tmp[(size_t)(n0 + r0) * 128 + col] =
                    make_float2(fmaxf(acc[j][0] + b.x, 0.f), fmaxf(acc[j][1] + b.y, 0.f));
            if (n0 + r1 < NN)
                *(float2*)&g_tmp[(size_t)(n0 + r1) * 128 + col] =
                    make_float2(fmaxf(acc[j][2] + b.x, 0.f), fmaxf(acc[j][3] + b.y, 0.f));
        }
        __syncthreads();
    }
}

/* ================= kernel C2: out = hidden@nw2+nb2 (MMA) + xupd ========== */
#define N2_WH 0
#define N2_WL 32768
#define N2_AH 65536
#define N2_AL 81920
#define N2_TOT 98304

__global__ void __launch_bounds__(512, 1)
k_node2(const float* __restrict__ nw2, const float* __restrict__ nb2,
        const float* __restrict__ x, float* __restrict__ out) {
    char* sm = smraw;
    int tid = threadIdx.x, lane = tid & 31, wid = tid >> 5;
    int wm = wid >> 2, wn = wid & 3;
    int gtid = blockIdx.x * 512 + tid;

    for (int i = gtid; i < NN * 3; i += GRIDN * 512)
        out[NN * 128 + i] = x[i] + g_dx[i] * (1.0f / (float)EE);

    for (int i = tid; i < 128 * 64; i += 512) {
        int n = i >> 6, kp = i & 63, k = 2 * kp;
        uint32_t off = (uint32_t)(n * 256) + pch(k >> 3, n) * 16 + (k & 7) * 2;
        uint32_t hw, lw;
        split2(nw2[k * 128 + n], nw2[(k + 1) * 128 + n], hw, lw);
        *(uint32_t*)(sm + N2_WH + off) = hw;
        *(uint32_t*)(sm + N2_WL + off) = lw;
    }
    __syncthreads();

    int r0 = 16 * wm + (lane >> 2), r1 = r0 + 8;

    for (int t = blockIdx.x; t < NTILES_N; t += GRIDN) {
        int n0 = t * 64;
        for (int i = tid; i < 64 * 64; i += 512) {
            int r = i >> 6, kp = i & 63, k = 2 * kp, n = n0 + r;
            float2 v = (n < NN) ? *(const float2*)&g_tmp[(size_t)n * 128 + k]
                                : make_float2(0.f, 0.f);
            uint32_t hw, lw; split2(v.x, v.y, hw, lw);
            uint32_t off = (uint32_t)(r * 256) + pch(k >> 3, r) * 16 + (k & 7) * 2;
            *(uint32_t*)(sm + N2_AH + off) = hw;
            *(uint32_t*)(sm + N2_AL + off) = lw;
        }
        __syncthreads();

        float acc[4][4];
#pragma unroll
        for (int j = 0; j < 4; j++)
#pragma unroll
            for (int q = 0; q < 4; q++) acc[j][q] = 0.f;
        mma_gemm<8, true, 256, 256, 1, 2>(sm + N2_AH, sm + N2_AL,
                                          sm + N2_WH, sm + N2_WL, acc, wm, wn, lane);
#pragma unroll
        for (int j = 0; j < 4; j++) {
            int col = 32 * wn + 8 * j + 2 * (lane & 3);
            float2 b = __ldg((const float2*)(nb2 + col));
            if (n0 + r0 < NN)
                *(float2*)&out[(size_t)(n0 + r0) * 128 + col] =
                    make_float2(acc[j][0] + b.x, acc[j][1] + b.y);
            if (n0 + r1 < NN)
                *(float2*)&out[(size_t)(n0 + r1) * 128 + col] =
                    make_float2(acc[j][2] + b.x, acc[j][3] + b.y);
        }
        __syncthreads();
    }
}

/* ========================================================================= */
extern "C" void kernel_launch(void* const* d_in, const int* in_sizes, int n_in,
                              void* d_out, int out_size) {
    const float* h    = (const float*)d_in[0];
    const float* x    = (const float*)d_in[1];
    const float* ea   = (const float*)d_in[2];
    const float* ew1  = (const float*)d_in[3];
    const float* eb1  = (const float*)d_in[4];
    const float* ew2  = (const float*)d_in[5];
    const float* eb2  = (const float*)d_in[6];
    const float* infw = (const float*)d_in[7];
    const float* infb = (const float*)d_in[8];
    const float* nw1  = (const float*)d_in[9];
    const float* nb1  = (const float*)d_in[10];
    const float* nw2  = (const float*)d_in[11];
    const float* nb2  = (const float*)d_in[12];
    const float* xw1  = (const float*)d_in[13];
    const float* xb1  = (const float*)d_in[14];
    const float* xw2  = (const float*)d_in[15];
    const float* xb2  = (const float*)d_in[16];
    const int*   ei   = (const int*)d_in[17];
    float* out = (float*)d_out;

    cudaFuncSetAttribute(k_node_pre, cudaFuncAttributeMaxDynamicSharedMemorySize, P_TOT);
    cudaFuncSetAttribute(k_edge,     cudaFuncAttributeMaxDynamicSharedMemorySize, SB_TOTAL);
    cudaFuncSetAttribute(k_node1,    cudaFuncAttributeMaxDynamicSharedMemorySize, N1_TOT);
    cudaFuncSetAttribute(k_node2,    cudaFuncAttributeMaxDynamicSharedMemorySize, N2_TOT);

    k_node_pre<<<GRIDN, 512, P_TOT>>>(h, ew1, eb1);
    k_edge<<<GRIDN, 512, SB_TOTAL>>>(x, ea, ew1, ew2, eb2, infw, infb,
                                     xw1, xb1, xw2, xb2, ei);
    k_node1<<<GRIDN, 512, N1_TOT>>>(h, nw1, nb1);
    k_node2<<<GRIDN, 512, N2_TOT>>>(nw2, nb2, x, out);
}